// round 5
// baseline (speedup 1.0000x reference)
#include <cuda_runtime.h>
#include <cuda_bf16.h>
#include <cstdint>

#define N_WG   512
#define MPAIR  256
#define NCOL   512
#define N_NODE (NCOL * MPAIR)
#define BATCH  8192

// ===========================================================================
// Packed f32x2 helpers
// ===========================================================================
typedef unsigned long long F2;
__device__ __forceinline__ F2 pk(float lo, float hi) {
    F2 r; asm("mov.b64 %0, {%1, %2};" : "=l"(r) : "f"(lo), "f"(hi)); return r;
}
__device__ __forceinline__ void un2(F2 v, float& lo, float& hi) {
    asm("mov.b64 {%0, %1}, %2;" : "=f"(lo), "=f"(hi) : "l"(v));
}
__device__ __forceinline__ F2 splat(float a) { return pk(a, a); }
__device__ __forceinline__ F2 fma2(F2 a, F2 b, F2 c) {
    F2 d; asm("fma.rn.f32x2 %0, %1, %2, %3;" : "=l"(d) : "l"(a), "l"(b), "l"(c)); return d;
}
__device__ __forceinline__ F2 mul2(F2 a, F2 b) {
    F2 d; asm("mul.rn.f32x2 %0, %1, %2;" : "=l"(d) : "l"(a), "l"(b)); return d;
}
__device__ __forceinline__ float2 cmul(float2 a, float2 b) {
    return make_float2(a.x * b.x - a.y * b.y, a.x * b.y + a.y * b.x);
}
__device__ __forceinline__ float2 cadd(float2 a, float2 b) {
    return make_float2(a.x + b.x, a.y + b.y);
}
__device__ __forceinline__ uint32_t smem_u32(const void* p) {
    uint32_t a;
    asm("{ .reg .u64 t; cvta.to.shared.u64 t, %1; cvt.u32.u64 %0, t; }" : "=r"(a) : "l"(p));
    return a;
}

// ===========================================================================
// Static scratch
// ===========================================================================
__device__ float2 g_U00[N_NODE], g_U01[N_NODE], g_U10[N_NODE], g_U11[N_NODE];
__device__ __align__(16) __nv_bfloat16 g_Gh[1024 * 512];
__device__ __align__(16) __nv_bfloat16 g_Gl[1024 * 512];
__device__ __align__(16) __nv_bfloat16 g_Xh[512 * 8192];
__device__ __align__(16) __nv_bfloat16 g_Xl[512 * 8192];

// ===========================================================================
// Kernel 1 (fused): blocks [0,4096) convert X fp32->bf16 hi/lo;
//                   blocks [4096,4608) build per-node 2x2 U.
// ===========================================================================
__global__ __launch_bounds__(256) void prep_kernel(
        const float4* __restrict__ X4,
        const float* __restrict__ th, const float* __restrict__ ph,
        const float* __restrict__ bse, const float* __restrict__ lse) {
    if (blockIdx.x < 4096) {
        int i = blockIdx.x * 256 + threadIdx.x;
        float4 v = X4[i];
        __nv_bfloat162 h0, h1, l0, l1;
        h0.x = __float2bfloat16(v.x); h0.y = __float2bfloat16(v.y);
        h1.x = __float2bfloat16(v.z); h1.y = __float2bfloat16(v.w);
        l0.x = __float2bfloat16(v.x - __bfloat162float(h0.x));
        l0.y = __float2bfloat16(v.y - __bfloat162float(h0.y));
        l1.x = __float2bfloat16(v.z - __bfloat162float(h1.x));
        l1.y = __float2bfloat16(v.w - __bfloat162float(h1.y));
        __nv_bfloat162* Xh2 = reinterpret_cast<__nv_bfloat162*>(g_Xh);
        __nv_bfloat162* Xl2 = reinterpret_cast<__nv_bfloat162*>(g_Xl);
        Xh2[2 * i] = h0; Xh2[2 * i + 1] = h1;
        Xl2[2 * i] = l0; Xl2[2 * i + 1] = l1;
        return;
    }
    int idx = (blockIdx.x - 4096) * 256 + threadIdx.x;
    int c = idx >> 8;
    int p = idx & 255;
    bool msk = ((c & 1) == 0) || (p < MPAIR - 1);

    float2 U00 = {1.f, 0.f}, U01 = {0.f, 0.f}, U10 = {0.f, 0.f}, U11 = {1.f, 0.f};
    if (msk) {
        float theta = th[idx], phi = ph[idx];
        float e0 = bse[2 * idx], e1 = bse[2 * idx + 1];
        float l0 = lse[2 * idx], l1 = lse[2 * idx + 1];
        const float KL = 0.11512925464970229f;  // ln(10)/20
        float ins0 = expf(l0 * KL), ins1 = expf(l1 * KL);
        const float PI4 = 0.7853981633974483f;
        float s0, c0, s1, c1;
        sincosf(PI4 + e0, &s0, &c0);
        sincosf(PI4 + e1, &s1, &c1);
        float2 EL, ET;
        sincosf(phi, &EL.y, &EL.x);
        sincosf(theta, &ET.y, &ET.x);
        float2 L11 = {ins0 * s0, 0.f}, L12 = {0.f, ins0 * c0}, L21 = {0.f, c0}, L22 = {s0, 0.f};
        float2 R11 = {ins1 * s1, 0.f}, R12 = {0.f, ins1 * c1}, R21 = {0.f, c1}, R22 = {s1, 0.f};
        float2 M00 = cmul(L11, cmul(EL, ET));
        float2 M10 = cmul(L12, EL);
        float2 M01 = cmul(L21, ET);
        float2 M11 = L22;
        U00 = cadd(cmul(R11, M00), cmul(R21, M10));
        U01 = cadd(cmul(R11, M01), cmul(R21, M11));
        U10 = cadd(cmul(R12, M00), cmul(R22, M10));
        U11 = cadd(cmul(R12, M01), cmul(R22, M11));
    }
    g_U00[idx] = U00; g_U01[idx] = U01; g_U10[idx] = U10; g_U11[idx] = U11;
}

// ===========================================================================
// Kernel 2: propagate identity*diag(e^{i gamma}) through mesh -> A (bf16 hi/lo).
// v2: prefetch depth 2 for U; ONE __syncthreads per odd column with redundant
// boundary-pair compute at warp edges (double-buffered smem hand-off).
// ===========================================================================
__device__ __forceinline__ void apply2(const F2* S, F2& tr, F2& ti, F2& br, F2& bi) {
    F2 ntr = fma2(S[5],  bi, fma2(S[3], br, fma2(S[2], ti, mul2(S[0], tr))));
    F2 nti = fma2(S[4],  br, fma2(S[3], bi, fma2(S[1], tr, mul2(S[0], ti))));
    F2 nbr = fma2(S[11], bi, fma2(S[9], br, fma2(S[8], ti, mul2(S[6], tr))));
    F2 nbi = fma2(S[10], br, fma2(S[9], bi, fma2(S[7], tr, mul2(S[6], ti))));
    tr = ntr; ti = nti; br = nbr; bi = nbi;
}

__device__ __forceinline__ void mk_S(F2* S, float2 u00, float2 u01, float2 u10, float2 u11) {
    S[0] = splat(u00.x); S[1]  = splat(u00.y); S[2]  = splat(-u00.y);
    S[3] = splat(u01.x); S[4]  = splat(u01.y); S[5]  = splat(-u01.y);
    S[6] = splat(u10.x); S[7]  = splat(u10.y); S[8]  = splat(-u10.y);
    S[9] = splat(u11.x); S[10] = splat(u11.y); S[11] = splat(-u11.y);
}

__device__ __forceinline__ void store_split(int row, int col, float a, float b) {
    __nv_bfloat16 ha = __float2bfloat16(a), hb = __float2bfloat16(b);
    __nv_bfloat16 la = __float2bfloat16(a - __bfloat162float(ha));
    __nv_bfloat16 lb = __float2bfloat16(b - __bfloat162float(hb));
    __nv_bfloat162 h; h.x = ha; h.y = hb;
    __nv_bfloat162 l; l.x = la; l.y = lb;
    *reinterpret_cast<__nv_bfloat162*>(&g_Gh[(size_t)row * 512 + col]) = h;
    *reinterpret_cast<__nv_bfloat162*>(&g_Gl[(size_t)row * 512 + col]) = l;
}

__global__ __launch_bounds__(256) void build_A(const float* __restrict__ gammas) {
    int r  = threadIdx.x;
    int jb = blockIdx.x * 4;
    int i0 = 2 * r, i1 = 2 * r + 1;
    int lane = r & 31, w = r >> 5;

    float sg0, cg0, sg1, cg1;
    sincosf(gammas[i0], &sg0, &cg0);
    sincosf(gammas[i1], &sg1, &cg1);

    F2 are[2], aim[2], bre[2], bim[2];
#pragma unroll
    for (int k = 0; k < 2; k++) {
        int j0 = jb + 2 * k, j1 = j0 + 1;
        are[k] = pk(i0 == j0 ? cg0 : 0.f, i0 == j1 ? cg0 : 0.f);
        aim[k] = pk(i0 == j0 ? sg0 : 0.f, i0 == j1 ? sg0 : 0.f);
        bre[k] = pk(i1 == j0 ? cg1 : 0.f, i1 == j1 ? cg1 : 0.f);
        bim[k] = pk(i1 == j0 ? sg1 : 0.f, i1 == j1 ? sg1 : 0.f);
    }

    // double-buffered boundary slots
    __shared__ F2     sPA[2][8][4];     // lane0's a (are0,are1,aim0,aim1)
    __shared__ F2     sPB[2][8][4];     // lane31's b
    __shared__ float2 sPU[2][8][4];     // lane31's U

    // U prefetch queue, depth 2
    float2 uc0 = g_U00[r],        uc1 = g_U01[r],        uc2 = g_U10[r],        uc3 = g_U11[r];
    float2 nx0 = g_U00[256 + r],  nx1 = g_U01[256 + r],  nx2 = g_U10[256 + r],  nx3 = g_U11[256 + r];

    for (int c = 0; c < NCOL; c++) {
        float2 p0, p1, p2, p3;
        if (c + 2 < NCOL) {
            int ni = ((c + 2) << 8) + r;
            p0 = g_U00[ni]; p1 = g_U01[ni]; p2 = g_U10[ni]; p3 = g_U11[ni];
        }
        F2 S[12];
        mk_S(S, uc0, uc1, uc2, uc3);

        if ((c & 1) == 0) {
#pragma unroll
            for (int k = 0; k < 2; k++)
                apply2(S, are[k], aim[k], bre[k], bim[k]);
        } else {
            int ob = (c >> 1) & 1;
            // publish boundary data (pre-odd-column values)
            if (lane == 0 && r > 0) {
                sPA[ob][w][0] = are[0]; sPA[ob][w][1] = are[1];
                sPA[ob][w][2] = aim[0]; sPA[ob][w][3] = aim[1];
            }
            if (lane == 31 && r < 255) {
                sPB[ob][w][0] = bre[0]; sPB[ob][w][1] = bre[1];
                sPB[ob][w][2] = bim[0]; sPB[ob][w][3] = bim[1];
                sPU[ob][w][0] = uc0; sPU[ob][w][1] = uc1;
                sPU[ob][w][2] = uc2; sPU[ob][w][3] = uc3;
            }
            __syncthreads();

            // fetch next thread's 'a' (row 2r+2)
            F2 nar[2], nai[2];
#pragma unroll
            for (int k = 0; k < 2; k++) {
                nar[k] = __shfl_down_sync(0xffffffffu, are[k], 1);
                nai[k] = __shfl_down_sync(0xffffffffu, aim[k], 1);
            }
            if (lane == 31 && r < 255) {
                nar[0] = sPA[ob][w + 1][0]; nar[1] = sPA[ob][w + 1][1];
                nai[0] = sPA[ob][w + 1][2]; nai[1] = sPA[ob][w + 1][3];
            }
            // compute pair p=r: (top = my b = row 2r+1, bottom = row 2r+2)
            if (r < 255) {
#pragma unroll
                for (int k = 0; k < 2; k++)
                    apply2(S, bre[k], bim[k], nar[k], nai[k]);
            }
            // pass updated row 2r+2 up to thread r+1
            F2 up0 = __shfl_up_sync(0xffffffffu, nar[0], 1);
            F2 up1 = __shfl_up_sync(0xffffffffu, nar[1], 1);
            F2 up2 = __shfl_up_sync(0xffffffffu, nai[0], 1);
            F2 up3 = __shfl_up_sync(0xffffffffu, nai[1], 1);
            if (lane >= 1) {
                are[0] = up0; are[1] = up1; aim[0] = up2; aim[1] = up3;
            } else if (r > 0) {
                // lane 0 (not thread 0): redundantly compute pair p=r-1 using
                // prev warp's published U and b -> updates my 'a' (row 2r).
                F2 SP[12];
                mk_S(SP, sPU[ob][w - 1][0], sPU[ob][w - 1][1],
                         sPU[ob][w - 1][2], sPU[ob][w - 1][3]);
                F2 pb0 = sPB[ob][w - 1][0], pb1 = sPB[ob][w - 1][1];
                F2 pb2 = sPB[ob][w - 1][2], pb3 = sPB[ob][w - 1][3];
                apply2(SP, pb0, pb2, are[0], aim[0]);
                apply2(SP, pb1, pb3, are[1], aim[1]);
            }
        }
        uc0 = nx0; uc1 = nx1; uc2 = nx2; uc3 = nx3;
        nx0 = p0;  nx1 = p1;  nx2 = p2;  nx3 = p3;
    }

    // emit bf16 hi/lo, m-major: rows [0,512)=Re, [512,1024)=Im
#pragma unroll
    for (int k = 0; k < 2; k++) {
        int j0 = jb + 2 * k;
        float x, y;
        un2(are[k], x, y); store_split(i0,       j0, x, y);
        un2(aim[k], x, y); store_split(512 + i0, j0, x, y);
        un2(bre[k], x, y); store_split(i1,       j0, x, y);
        un2(bim[k], x, y); store_split(512 + i1, j0, x, y);
    }
}

// ===========================================================================
// Kernel 3: mma.sync bf16 GEMM. out = Gh@Xh + Gh@Xl + Gl@Xh (fp32 accum).
// CTA 128x128, BK=32, 3-stage cp.async pipeline, 8 warps (32x64 each).
// ===========================================================================
__device__ __forceinline__ void ldmx4(uint32_t* r, uint32_t addr) {
    asm volatile("ldmatrix.sync.aligned.m8n8.x4.shared.b16 {%0,%1,%2,%3}, [%4];"
                 : "=r"(r[0]), "=r"(r[1]), "=r"(r[2]), "=r"(r[3]) : "r"(addr));
}
__device__ __forceinline__ void ldmx4t(uint32_t* r, uint32_t addr) {
    asm volatile("ldmatrix.sync.aligned.m8n8.x4.trans.shared.b16 {%0,%1,%2,%3}, [%4];"
                 : "=r"(r[0]), "=r"(r[1]), "=r"(r[2]), "=r"(r[3]) : "r"(addr));
}
__device__ __forceinline__ void mma_bf16(float* c, const uint32_t* a, uint32_t b0, uint32_t b1) {
    asm volatile("mma.sync.aligned.m16n8k16.row.col.f32.bf16.bf16.f32 "
                 "{%0,%1,%2,%3}, {%4,%5,%6,%7}, {%8,%9}, {%0,%1,%2,%3};"
                 : "+f"(c[0]), "+f"(c[1]), "+f"(c[2]), "+f"(c[3])
                 : "r"(a[0]), "r"(a[1]), "r"(a[2]), "r"(a[3]), "r"(b0), "r"(b1));
}

__global__ __launch_bounds__(256, 2) void mma_gemm(float* __restrict__ out) {
    __shared__ __align__(1024) char raw[3 * 16384];
    uint32_t sbase = smem_u32(raw);

    int tid = threadIdx.x;
    int lane = tid & 31, wid = tid >> 5;
    int wm = wid & 3, wn = wid >> 2;
    int bm = blockIdx.y * 128, bn = blockIdx.x * 128;

    auto issue = [&](int st, int buf) {
        int p = st >> 4;
        int kblk = (st & 15) << 5;
        const __nv_bfloat16* Ap = (p == 2) ? g_Gl : g_Gh;
        const __nv_bfloat16* Bp = (p == 1) ? g_Xl : g_Xh;
        uint32_t base = sbase + buf * 16384;
#pragma unroll
        for (int h = 0; h < 2; h++) {
            int cA = tid + h * 256;
            int row = cA >> 2, kc = cA & 3;
            uint32_t dA = base + row * 64 + ((kc ^ ((row >> 1) & 3)) << 4);
            const __nv_bfloat16* sA = Ap + (size_t)(bm + row) * 512 + kblk + kc * 8;
            asm volatile("cp.async.cg.shared.global [%0], [%1], 16;" :: "r"(dA), "l"(sA));
            int cB = tid + h * 256;
            int k = cB >> 4, nch = cB & 15;
            uint32_t dB = base + 8192 + k * 256 + ((nch ^ (k & 7)) << 4);
            const __nv_bfloat16* sB = Bp + (size_t)(kblk + k) * 8192 + bn + nch * 8;
            asm volatile("cp.async.cg.shared.global [%0], [%1], 16;" :: "r"(dB), "l"(sB));
        }
        asm volatile("cp.async.commit_group;" ::: "memory");
    };

    int grp = lane >> 3, lrow = lane & 7;
    int g1 = grp & 1, g2 = grp >> 1;
    int arow = wm * 32 + g1 * 8 + lrow;
    uint32_t aBase = arow * 64 + ((g2 ^ (lrow >> 1)) << 4);
    int bk = g1 * 8 + lrow;
    uint32_t bBase = 8192 + bk * 256 + wn * 128 + ((g2 ^ lrow) << 4);

    float acc[2][8][4];
#pragma unroll
    for (int mt = 0; mt < 2; mt++)
#pragma unroll
        for (int nj = 0; nj < 8; nj++)
#pragma unroll
            for (int q = 0; q < 4; q++) acc[mt][nj][q] = 0.f;

    issue(0, 0);
    issue(1, 1);

#pragma unroll 1
    for (int st = 0; st < 48; st++) {
        int buf = st % 3;
        if (st < 47) asm volatile("cp.async.wait_group 1;" ::: "memory");
        else         asm volatile("cp.async.wait_group 0;" ::: "memory");
        __syncthreads();
        if (st + 2 < 48) issue(st + 2, (st + 2) % 3);

        uint32_t stage = sbase + buf * 16384;
#pragma unroll
        for (int s = 0; s < 2; s++) {
            uint32_t a[2][4];
            ldmx4(a[0], (stage + aBase) ^ (s << 5));
            ldmx4(a[1], (stage + aBase + 16 * 64) ^ (s << 5));
#pragma unroll
            for (int j2 = 0; j2 < 4; j2++) {
                uint32_t b[4];
                ldmx4t(b, (stage + bBase + (s << 12)) ^ (j2 << 5));
#pragma unroll
                for (int mt = 0; mt < 2; mt++) {
                    mma_bf16(acc[mt][2 * j2],     a[mt], b[0], b[1]);
                    mma_bf16(acc[mt][2 * j2 + 1], a[mt], b[2], b[3]);
                }
            }
        }
    }

    int mrow = bm + wm * 32 + (lane >> 2);
    int ncol = bn + wn * 64 + (lane & 3) * 2;
#pragma unroll
    for (int mt = 0; mt < 2; mt++) {
#pragma unroll
        for (int nj = 0; nj < 8; nj++) {
            float* o = out + (size_t)(mrow + mt * 16) * 8192 + ncol + nj * 8;
            *reinterpret_cast<float2*>(o)             = make_float2(acc[mt][nj][0], acc[mt][nj][1]);
            *reinterpret_cast<float2*>(o + 8 * 8192)  = make_float2(acc[mt][nj][2], acc[mt][nj][3]);
        }
    }
}

// ===========================================================================
// Launch
// ===========================================================================
extern "C" void kernel_launch(void* const* d_in, const int* in_sizes, int n_in,
                              void* d_out, int out_size) {
    const float* x      = (const float*)d_in[0];
    const float* thetas = (const float*)d_in[1];
    const float* phis   = (const float*)d_in[2];
    const float* gammas = (const float*)d_in[3];
    const float* bse    = (const float*)d_in[4];
    const float* lse    = (const float*)d_in[5];
    (void)in_sizes; (void)n_in; (void)out_size;

    prep_kernel<<<4096 + 512, 256>>>((const float4*)x, thetas, phis, bse, lse);
    build_A<<<128, 256>>>(gammas);
    mma_gemm<<<dim3(64, 8), 256>>>((float*)d_out);
}

// round 6
// speedup vs baseline: 1.1994x; 1.1994x over previous
#include <cuda_runtime.h>
#include <cuda_bf16.h>
#include <cstdint>

#define N_WG   512
#define MPAIR  256
#define NCOL   512
#define N_NODE (NCOL * MPAIR)
#define BATCH  8192

// ===========================================================================
// Packed f32x2 helpers
// ===========================================================================
typedef unsigned long long F2;
__device__ __forceinline__ F2 pk(float lo, float hi) {
    F2 r; asm("mov.b64 %0, {%1, %2};" : "=l"(r) : "f"(lo), "f"(hi)); return r;
}
__device__ __forceinline__ void un2(F2 v, float& lo, float& hi) {
    asm("mov.b64 {%0, %1}, %2;" : "=f"(lo), "=f"(hi) : "l"(v));
}
__device__ __forceinline__ F2 splat(float a) { return pk(a, a); }
__device__ __forceinline__ F2 fma2(F2 a, F2 b, F2 c) {
    F2 d; asm("fma.rn.f32x2 %0, %1, %2, %3;" : "=l"(d) : "l"(a), "l"(b), "l"(c)); return d;
}
__device__ __forceinline__ F2 mul2(F2 a, F2 b) {
    F2 d; asm("mul.rn.f32x2 %0, %1, %2;" : "=l"(d) : "l"(a), "l"(b)); return d;
}
__device__ __forceinline__ float2 cmul(float2 a, float2 b) {
    return make_float2(a.x * b.x - a.y * b.y, a.x * b.y + a.y * b.x);
}
__device__ __forceinline__ float2 cadd(float2 a, float2 b) {
    return make_float2(a.x + b.x, a.y + b.y);
}
__device__ __forceinline__ uint32_t smem_u32(const void* p) {
    uint32_t a;
    asm("{ .reg .u64 t; cvta.to.shared.u64 t, %1; cvt.u32.u64 %0, t; }" : "=r"(a) : "l"(p));
    return a;
}

// ===========================================================================
// Static scratch
// ===========================================================================
__device__ float2 g_U00[N_NODE], g_U01[N_NODE], g_U10[N_NODE], g_U11[N_NODE];
__device__ __align__(16) __nv_bfloat16 g_Gh[1024 * 512];
__device__ __align__(16) __nv_bfloat16 g_Gl[1024 * 512];
__device__ __align__(16) __nv_bfloat16 g_Xh[512 * 8192];
__device__ __align__(16) __nv_bfloat16 g_Xl[512 * 8192];

// ===========================================================================
// Kernel 1 (fused): blocks [0,4096) convert X fp32->bf16 hi/lo;
//                   blocks [4096,4608) build per-node 2x2 U.
// ===========================================================================
__global__ __launch_bounds__(256) void prep_kernel(
        const float4* __restrict__ X4,
        const float* __restrict__ th, const float* __restrict__ ph,
        const float* __restrict__ bse, const float* __restrict__ lse) {
    if (blockIdx.x < 4096) {
        int i = blockIdx.x * 256 + threadIdx.x;
        float4 v = X4[i];
        __nv_bfloat162 h0, h1, l0, l1;
        h0.x = __float2bfloat16(v.x); h0.y = __float2bfloat16(v.y);
        h1.x = __float2bfloat16(v.z); h1.y = __float2bfloat16(v.w);
        l0.x = __float2bfloat16(v.x - __bfloat162float(h0.x));
        l0.y = __float2bfloat16(v.y - __bfloat162float(h0.y));
        l1.x = __float2bfloat16(v.z - __bfloat162float(h1.x));
        l1.y = __float2bfloat16(v.w - __bfloat162float(h1.y));
        __nv_bfloat162* Xh2 = reinterpret_cast<__nv_bfloat162*>(g_Xh);
        __nv_bfloat162* Xl2 = reinterpret_cast<__nv_bfloat162*>(g_Xl);
        Xh2[2 * i] = h0; Xh2[2 * i + 1] = h1;
        Xl2[2 * i] = l0; Xl2[2 * i + 1] = l1;
        return;
    }
    int idx = (blockIdx.x - 4096) * 256 + threadIdx.x;
    int c = idx >> 8;
    int p = idx & 255;
    bool msk = ((c & 1) == 0) || (p < MPAIR - 1);

    float2 U00 = {1.f, 0.f}, U01 = {0.f, 0.f}, U10 = {0.f, 0.f}, U11 = {1.f, 0.f};
    if (msk) {
        float theta = th[idx], phi = ph[idx];
        float e0 = bse[2 * idx], e1 = bse[2 * idx + 1];
        float l0 = lse[2 * idx], l1 = lse[2 * idx + 1];
        const float KL = 0.11512925464970229f;  // ln(10)/20
        float ins0 = expf(l0 * KL), ins1 = expf(l1 * KL);
        const float PI4 = 0.7853981633974483f;
        float s0, c0, s1, c1;
        sincosf(PI4 + e0, &s0, &c0);
        sincosf(PI4 + e1, &s1, &c1);
        float2 EL, ET;
        sincosf(phi, &EL.y, &EL.x);
        sincosf(theta, &ET.y, &ET.x);
        float2 L11 = {ins0 * s0, 0.f}, L12 = {0.f, ins0 * c0}, L21 = {0.f, c0}, L22 = {s0, 0.f};
        float2 R11 = {ins1 * s1, 0.f}, R12 = {0.f, ins1 * c1}, R21 = {0.f, c1}, R22 = {s1, 0.f};
        float2 M00 = cmul(L11, cmul(EL, ET));
        float2 M10 = cmul(L12, EL);
        float2 M01 = cmul(L21, ET);
        float2 M11 = L22;
        U00 = cadd(cmul(R11, M00), cmul(R21, M10));
        U01 = cadd(cmul(R11, M01), cmul(R21, M11));
        U10 = cadd(cmul(R12, M00), cmul(R22, M10));
        U11 = cadd(cmul(R12, M01), cmul(R22, M11));
    }
    g_U00[idx] = U00; g_U01[idx] = U01; g_U10[idx] = U10; g_U11[idx] = U11;
}

// ===========================================================================
// Kernel 2: propagate identity*diag(e^{i gamma}) through mesh -> A (bf16 hi/lo).
// Round-3 structure (two barriers per odd column, no divergent redundant
// compute) + U prefetch depth 2 ONLY.
// ===========================================================================
__device__ __forceinline__ void apply2(const F2* S, F2& tr, F2& ti, F2& br, F2& bi) {
    F2 ntr = fma2(S[5],  bi, fma2(S[3], br, fma2(S[2], ti, mul2(S[0], tr))));
    F2 nti = fma2(S[4],  br, fma2(S[3], bi, fma2(S[1], tr, mul2(S[0], ti))));
    F2 nbr = fma2(S[11], bi, fma2(S[9], br, fma2(S[8], ti, mul2(S[6], tr))));
    F2 nbi = fma2(S[10], br, fma2(S[9], bi, fma2(S[7], tr, mul2(S[6], ti))));
    tr = ntr; ti = nti; br = nbr; bi = nbi;
}

__device__ __forceinline__ void store_split(int row, int col, float a, float b) {
    __nv_bfloat16 ha = __float2bfloat16(a), hb = __float2bfloat16(b);
    __nv_bfloat16 la = __float2bfloat16(a - __bfloat162float(ha));
    __nv_bfloat16 lb = __float2bfloat16(b - __bfloat162float(hb));
    __nv_bfloat162 h; h.x = ha; h.y = hb;
    __nv_bfloat162 l; l.x = la; l.y = lb;
    *reinterpret_cast<__nv_bfloat162*>(&g_Gh[(size_t)row * 512 + col]) = h;
    *reinterpret_cast<__nv_bfloat162*>(&g_Gl[(size_t)row * 512 + col]) = l;
}

__global__ __launch_bounds__(256) void build_A(const float* __restrict__ gammas) {
    int r  = threadIdx.x;
    int jb = blockIdx.x * 4;
    int i0 = 2 * r, i1 = 2 * r + 1;
    int lane = r & 31, w = r >> 5;

    float sg0, cg0, sg1, cg1;
    sincosf(gammas[i0], &sg0, &cg0);
    sincosf(gammas[i1], &sg1, &cg1);

    F2 are[2], aim[2], bre[2], bim[2];
#pragma unroll
    for (int k = 0; k < 2; k++) {
        int j0 = jb + 2 * k, j1 = j0 + 1;
        are[k] = pk(i0 == j0 ? cg0 : 0.f, i0 == j1 ? cg0 : 0.f);
        aim[k] = pk(i0 == j0 ? sg0 : 0.f, i0 == j1 ? sg0 : 0.f);
        bre[k] = pk(i1 == j0 ? cg1 : 0.f, i1 == j1 ? cg1 : 0.f);
        bim[k] = pk(i1 == j0 ? sg1 : 0.f, i1 == j1 ? sg1 : 0.f);
    }

    __shared__ F2 sEA[8][4];
    __shared__ F2 sEB[8][4];

    // U prefetch queue, depth 2
    float2 uc0 = g_U00[r],       uc1 = g_U01[r],       uc2 = g_U10[r],       uc3 = g_U11[r];
    float2 nx0 = g_U00[256 + r], nx1 = g_U01[256 + r], nx2 = g_U10[256 + r], nx3 = g_U11[256 + r];

    for (int c = 0; c < NCOL; c++) {
        float2 pf0, pf1, pf2, pf3;
        if (c + 2 < NCOL) {
            int ni = ((c + 2) << 8) + r;
            pf0 = g_U00[ni]; pf1 = g_U01[ni]; pf2 = g_U10[ni]; pf3 = g_U11[ni];
        }
        F2 S[12] = {
            splat(uc0.x), splat(uc0.y), splat(-uc0.y),
            splat(uc1.x), splat(uc1.y), splat(-uc1.y),
            splat(uc2.x), splat(uc2.y), splat(-uc2.y),
            splat(uc3.x), splat(uc3.y), splat(-uc3.y)
        };
        if ((c & 1) == 0) {
#pragma unroll
            for (int k = 0; k < 2; k++)
                apply2(S, are[k], aim[k], bre[k], bim[k]);
        } else {
            // pair p=r couples (row 2r+1 = my b, row 2r+2 = neighbor's a)
            F2 nar[2], nai[2];
#pragma unroll
            for (int k = 0; k < 2; k++) {
                nar[k] = __shfl_down_sync(0xffffffffu, are[k], 1);
                nai[k] = __shfl_down_sync(0xffffffffu, aim[k], 1);
            }
            if (lane == 0 && r > 0) {
                sEA[w][0] = are[0]; sEA[w][1] = are[1];
                sEA[w][2] = aim[0]; sEA[w][3] = aim[1];
            }
            __syncthreads();
            if (lane == 31 && r < 255) {
                nar[0] = sEA[w + 1][0]; nar[1] = sEA[w + 1][1];
                nai[0] = sEA[w + 1][2]; nai[1] = sEA[w + 1][3];
            }
            if (r < 255) {
#pragma unroll
                for (int k = 0; k < 2; k++)
                    apply2(S, bre[k], bim[k], nar[k], nai[k]);
            }
            // return updated bottom row (2r+2) to thread r+1's 'a'
            F2 up0 = __shfl_up_sync(0xffffffffu, nar[0], 1);
            F2 up1 = __shfl_up_sync(0xffffffffu, nar[1], 1);
            F2 up2 = __shfl_up_sync(0xffffffffu, nai[0], 1);
            F2 up3 = __shfl_up_sync(0xffffffffu, nai[1], 1);
            if (lane == 31 && r < 255) {
                sEB[w + 1][0] = nar[0]; sEB[w + 1][1] = nar[1];
                sEB[w + 1][2] = nai[0]; sEB[w + 1][3] = nai[1];
            }
            __syncthreads();
            if (r > 0) {
                if (lane == 0) {
                    are[0] = sEB[w][0]; are[1] = sEB[w][1];
                    aim[0] = sEB[w][2]; aim[1] = sEB[w][3];
                } else {
                    are[0] = up0; are[1] = up1; aim[0] = up2; aim[1] = up3;
                }
            }
        }
        uc0 = nx0; uc1 = nx1; uc2 = nx2; uc3 = nx3;
        nx0 = pf0; nx1 = pf1; nx2 = pf2; nx3 = pf3;
    }

    // emit bf16 hi/lo, m-major: rows [0,512)=Re, [512,1024)=Im
#pragma unroll
    for (int k = 0; k < 2; k++) {
        int j0 = jb + 2 * k;
        float x, y;
        un2(are[k], x, y); store_split(i0,       j0, x, y);
        un2(aim[k], x, y); store_split(512 + i0, j0, x, y);
        un2(bre[k], x, y); store_split(i1,       j0, x, y);
        un2(bim[k], x, y); store_split(512 + i1, j0, x, y);
    }
}

// ===========================================================================
// Kernel 3: mma.sync bf16 GEMM. out = Gh@Xh + Gh@Xl + Gl@Xh (fp32 accum).
// CTA 128x128, BK=32, 3-stage cp.async pipeline, 8 warps (32x64 each).
// ===========================================================================
__device__ __forceinline__ void ldmx4(uint32_t* r, uint32_t addr) {
    asm volatile("ldmatrix.sync.aligned.m8n8.x4.shared.b16 {%0,%1,%2,%3}, [%4];"
                 : "=r"(r[0]), "=r"(r[1]), "=r"(r[2]), "=r"(r[3]) : "r"(addr));
}
__device__ __forceinline__ void ldmx4t(uint32_t* r, uint32_t addr) {
    asm volatile("ldmatrix.sync.aligned.m8n8.x4.trans.shared.b16 {%0,%1,%2,%3}, [%4];"
                 : "=r"(r[0]), "=r"(r[1]), "=r"(r[2]), "=r"(r[3]) : "r"(addr));
}
__device__ __forceinline__ void mma_bf16(float* c, const uint32_t* a, uint32_t b0, uint32_t b1) {
    asm volatile("mma.sync.aligned.m16n8k16.row.col.f32.bf16.bf16.f32 "
                 "{%0,%1,%2,%3}, {%4,%5,%6,%7}, {%8,%9}, {%0,%1,%2,%3};"
                 : "+f"(c[0]), "+f"(c[1]), "+f"(c[2]), "+f"(c[3])
                 : "r"(a[0]), "r"(a[1]), "r"(a[2]), "r"(a[3]), "r"(b0), "r"(b1));
}

__global__ __launch_bounds__(256, 2) void mma_gemm(float* __restrict__ out) {
    __shared__ __align__(1024) char raw[3 * 16384];
    uint32_t sbase = smem_u32(raw);

    int tid = threadIdx.x;
    int lane = tid & 31, wid = tid >> 5;
    int wm = wid & 3, wn = wid >> 2;
    int bm = blockIdx.y * 128, bn = blockIdx.x * 128;

    auto issue = [&](int st, int buf) {
        int p = st >> 4;
        int kblk = (st & 15) << 5;
        const __nv_bfloat16* Ap = (p == 2) ? g_Gl : g_Gh;
        const __nv_bfloat16* Bp = (p == 1) ? g_Xl : g_Xh;
        uint32_t base = sbase + buf * 16384;
#pragma unroll
        for (int h = 0; h < 2; h++) {
            int cA = tid + h * 256;
            int row = cA >> 2, kc = cA & 3;
            uint32_t dA = base + row * 64 + ((kc ^ ((row >> 1) & 3)) << 4);
            const __nv_bfloat16* sA = Ap + (size_t)(bm + row) * 512 + kblk + kc * 8;
            asm volatile("cp.async.cg.shared.global [%0], [%1], 16;" :: "r"(dA), "l"(sA));
            int cB = tid + h * 256;
            int k = cB >> 4, nch = cB & 15;
            uint32_t dB = base + 8192 + k * 256 + ((nch ^ (k & 7)) << 4);
            const __nv_bfloat16* sB = Bp + (size_t)(kblk + k) * 8192 + bn + nch * 8;
            asm volatile("cp.async.cg.shared.global [%0], [%1], 16;" :: "r"(dB), "l"(sB));
        }
        asm volatile("cp.async.commit_group;" ::: "memory");
    };

    int grp = lane >> 3, lrow = lane & 7;
    int g1 = grp & 1, g2 = grp >> 1;
    int arow = wm * 32 + g1 * 8 + lrow;
    uint32_t aBase = arow * 64 + ((g2 ^ (lrow >> 1)) << 4);
    int bk = g1 * 8 + lrow;
    uint32_t bBase = 8192 + bk * 256 + wn * 128 + ((g2 ^ lrow) << 4);

    float acc[2][8][4];
#pragma unroll
    for (int mt = 0; mt < 2; mt++)
#pragma unroll
        for (int nj = 0; nj < 8; nj++)
#pragma unroll
            for (int q = 0; q < 4; q++) acc[mt][nj][q] = 0.f;

    issue(0, 0);
    issue(1, 1);

#pragma unroll 1
    for (int st = 0; st < 48; st++) {
        int buf = st % 3;
        if (st < 47) asm volatile("cp.async.wait_group 1;" ::: "memory");
        else         asm volatile("cp.async.wait_group 0;" ::: "memory");
        __syncthreads();
        if (st + 2 < 48) issue(st + 2, (st + 2) % 3);

        uint32_t stage = sbase + buf * 16384;
#pragma unroll
        for (int s = 0; s < 2; s++) {
            uint32_t a[2][4];
            ldmx4(a[0], (stage + aBase) ^ (s << 5));
            ldmx4(a[1], (stage + aBase + 16 * 64) ^ (s << 5));
#pragma unroll
            for (int j2 = 0; j2 < 4; j2++) {
                uint32_t b[4];
                ldmx4t(b, (stage + bBase + (s << 12)) ^ (j2 << 5));
#pragma unroll
                for (int mt = 0; mt < 2; mt++) {
                    mma_bf16(acc[mt][2 * j2],     a[mt], b[0], b[1]);
                    mma_bf16(acc[mt][2 * j2 + 1], a[mt], b[2], b[3]);
                }
            }
        }
    }

    int mrow = bm + wm * 32 + (lane >> 2);
    int ncol = bn + wn * 64 + (lane & 3) * 2;
#pragma unroll
    for (int mt = 0; mt < 2; mt++) {
#pragma unroll
        for (int nj = 0; nj < 8; nj++) {
            float* o = out + (size_t)(mrow + mt * 16) * 8192 + ncol + nj * 8;
            *reinterpret_cast<float2*>(o)             = make_float2(acc[mt][nj][0], acc[mt][nj][1]);
            *reinterpret_cast<float2*>(o + 8 * 8192)  = make_float2(acc[mt][nj][2], acc[mt][nj][3]);
        }
    }
}

// ===========================================================================
// Launch
// ===========================================================================
extern "C" void kernel_launch(void* const* d_in, const int* in_sizes, int n_in,
                              void* d_out, int out_size) {
    const float* x      = (const float*)d_in[0];
    const float* thetas = (const float*)d_in[1];
    const float* phis   = (const float*)d_in[2];
    const float* gammas = (const float*)d_in[3];
    const float* bse    = (const float*)d_in[4];
    const float* lse    = (const float*)d_in[5];
    (void)in_sizes; (void)n_in; (void)out_size;

    prep_kernel<<<4096 + 512, 256>>>((const float4*)x, thetas, phis, bse, lse);
    build_A<<<128, 256>>>(gammas);
    mma_gemm<<<dim3(64, 8), 256>>>((float*)d_out);
}